// round 7
// baseline (speedup 1.0000x reference)
#include <cuda_runtime.h>
#include <cuda_bf16.h>
#include <cstdint>
#include <cstddef>

// Problem constants
#define NN     100000
#define NPAD   100096            // 782 * 128
#define NREL8  8
#define NRELT  16
#define DD     256
#define EE     262144            // 2^18
#define KTOT   (NRELT * DD)      // 4096
#define NB     (NRELT * NPAD)    // 1601536 bins
#define NBLK   (NB / 256)        // 6256

// GEMM tiling: CTA 128(M) x 256(N), BK=64, 2 stages
#define STAGE  98304
#define A_HI   0
#define A_LO   16384
#define B_HI   32768
#define B_LO   65536
#define SMEM_GEMM (2 * STAGE + 1024)

// ---------------- scratch (static device globals) --------------------------
__device__ __align__(16) __nv_bfloat16 g_Yhi[(size_t)NPAD * KTOT];  // 820 MB
__device__ __align__(16) __nv_bfloat16 g_Ylo[(size_t)NPAD * KTOT];  // 820 MB
__device__ __align__(16) __nv_bfloat16 g_Whi[(size_t)DD * KTOT];    // B^T: [n][kk]
__device__ __align__(16) __nv_bfloat16 g_Wlo[(size_t)DD * KTOT];
__device__ int   g_degi[NB];
__device__ int   g_roff[NB];
__device__ int   g_cur[NB];
__device__ int   g_bsum[NBLK];
__device__ int   g_ecol[NRELT * EE];
__device__ float g_scale[NB];                // invfull[r] * invdeg_i[r]
__device__ float g_invfull[NPAD];
__device__ unsigned g_indmask[NPAD];
__device__ __align__(16) float g_bW[NRELT * DD];

// ---------------- helpers ---------------------------------------------------
__device__ __forceinline__ uint32_t sw128(uint32_t o) { return o ^ ((o >> 3) & 0x70); }
__device__ __forceinline__ uint32_t pack_bf2(__nv_bfloat16 a, __nv_bfloat16 b) {
    return ((uint32_t)__bfloat16_as_ushort(b) << 16) | (uint32_t)__bfloat16_as_ushort(a);
}
__device__ __forceinline__ void cp16(uint32_t s, const void* g) {
    asm volatile("cp.async.cg.shared.global [%0], [%1], 16;"
                 :: "r"(s), "l"(__cvta_generic_to_global(g)) : "memory");
}
__device__ __forceinline__ void ldsm4(uint32_t r[4], uint32_t addr) {
    asm volatile("ldmatrix.sync.aligned.m8n8.x4.shared.b16 {%0,%1,%2,%3}, [%4];"
                 : "=r"(r[0]), "=r"(r[1]), "=r"(r[2]), "=r"(r[3]) : "r"(addr));
}
__device__ __forceinline__ void mma_bf16(float d[4], const uint32_t a[4],
                                         uint32_t b0, uint32_t b1) {
    asm volatile(
        "mma.sync.aligned.m16n8k16.row.col.f32.bf16.bf16.f32 "
        "{%0,%1,%2,%3}, {%4,%5,%6,%7}, {%8,%9}, {%0,%1,%2,%3};"
        : "+f"(d[0]), "+f"(d[1]), "+f"(d[2]), "+f"(d[3])
        : "r"(a[0]), "r"(a[1]), "r"(a[2]), "r"(a[3]), "r"(b0), "r"(b1));
}

// ---------------- CSR build --------------------------------------------------
__global__ void k_zdeg() {
    g_degi[blockIdx.x * blockDim.x + threadIdx.x] = 0;
}

__global__ void k_deg(const int* __restrict__ adj_row,
                      const int* __restrict__ adj_t_row) {
    int idx = blockIdx.x * blockDim.x + threadIdx.x;
    int rel = idx >> 18;
    int e   = idx & (EE - 1);
    int r = (rel < NREL8) ? __ldg(&adj_row[rel * EE + e])
                          : __ldg(&adj_t_row[(rel - NREL8) * EE + e]);
    atomicAdd(&g_degi[rel * NPAD + r], 1);
}

__global__ void k_scanA() {
    __shared__ int sh[256];
    int b = blockIdx.x, t = threadIdx.x;
    int v = g_degi[b * 256 + t];
    sh[t] = v; __syncthreads();
    #pragma unroll
    for (int o = 1; o < 256; o <<= 1) {
        int x = (t >= o) ? sh[t - o] : 0;
        __syncthreads();
        sh[t] += x;
        __syncthreads();
    }
    g_roff[b * 256 + t] = sh[t] - v;
    if (t == 255) g_bsum[b] = sh[255];
}

__global__ void k_scanB() {
    __shared__ int sh[256];
    __shared__ int run;
    int t = threadIdx.x;
    if (t == 0) run = 0;
    __syncthreads();
    for (int base = 0; base < NBLK; base += 256) {
        int idx = base + t;
        int v = (idx < NBLK) ? g_bsum[idx] : 0;
        sh[t] = v; __syncthreads();
        #pragma unroll
        for (int o = 1; o < 256; o <<= 1) {
            int x = (t >= o) ? sh[t - o] : 0;
            __syncthreads();
            sh[t] += x;
            __syncthreads();
        }
        if (idx < NBLK) g_bsum[idx] = run + sh[t] - v;
        __syncthreads();
        if (t == 255) run += sh[255];
        __syncthreads();
    }
}

__global__ void k_scanC() {
    int i = blockIdx.x * 256 + threadIdx.x;
    int v = g_roff[i] + g_bsum[i >> 8];
    g_roff[i] = v;
    g_cur[i]  = v;
}

__global__ void k_ecol(const int* __restrict__ adj_row, const int* __restrict__ adj_col,
                       const int* __restrict__ adj_t_row, const int* __restrict__ adj_t_col) {
    int idx = blockIdx.x * blockDim.x + threadIdx.x;
    int rel = idx >> 18;
    int e   = idx & (EE - 1);
    int r, c;
    if (rel < NREL8) {
        r = __ldg(&adj_row[rel * EE + e]);
        c = __ldg(&adj_col[rel * EE + e]);
    } else {
        int rr = rel - NREL8;
        r = __ldg(&adj_t_row[rr * EE + e]);
        c = __ldg(&adj_t_col[rr * EE + e]);
    }
    int pos = atomicAdd(&g_cur[rel * NPAD + r], 1);
    g_ecol[pos] = c;
}

// ---------------- norms / bias ------------------------------------------------
__global__ void k_norm() {
    int m = blockIdx.x * blockDim.x + threadIdx.x;
    if (m >= NPAD) return;
    float full = 0.f;
    unsigned mask = 0;
    float inv[NRELT];
    #pragma unroll
    for (int i = 0; i < NRELT; i++) {
        int d = g_degi[i * NPAD + m];
        if (d > 0) { full += 1.f; mask |= (1u << i); inv[i] = 1.f / (float)d; }
        else inv[i] = 1.f;
    }
    float invf = (full > 0.f) ? (1.f / full) : 1.f;
    g_invfull[m] = invf;
    g_indmask[m] = mask;
    #pragma unroll
    for (int i = 0; i < NRELT; i++) g_scale[i * NPAD + m] = invf * inv[i];
}

__global__ void k_bw(const float* __restrict__ bias, const float* __restrict__ w,
                     const float* __restrict__ bias_t, const float* __restrict__ w_t) {
    int i = blockIdx.x;
    int n = threadIdx.x;
    const float* b = (i < NREL8) ? (bias + i * DD) : (bias_t + (i - NREL8) * DD);
    const float* W = (i < NREL8) ? (w + (size_t)i * DD * DD)
                                 : (w_t + (size_t)(i - NREL8) * DD * DD);
    float s = 0.f;
    for (int k = 0; k < DD; k++) s += b[k] * W[(size_t)k * DD + n];
    g_bW[i * DD + n] = s;
}

// Split W into bf16 hi/lo, B^T layout: g_Whi[n*4096 + rel*256 + k] = W_rel[k][n]
__global__ void k_prepW(const float* __restrict__ w, const float* __restrict__ w_t) {
    int idx = blockIdx.x * blockDim.x + threadIdx.x;   // DD*KTOT = 1048576
    int n   = idx >> 12;
    int kk  = idx & 4095;
    int rel = kk >> 8;
    int k   = kk & 255;
    const float* W = (rel < NREL8) ? (w + (size_t)rel * DD * DD)
                                   : (w_t + (size_t)(rel - NREL8) * DD * DD);
    float x = W[(size_t)k * DD + n];
    __nv_bfloat16 h = __float2bfloat16(x);
    g_Whi[idx] = h;
    g_Wlo[idx] = __float2bfloat16(x - __bfloat162float(h));
}

// out[m][:] = invfull[m] * sum_{i: deg_i[m]>0} bW_i[:]  (bias base; GEMM adds)
__global__ void k_init(float* __restrict__ out) {
    __shared__ float4 bws[NRELT * 64];
    int tid = threadIdx.x;
    for (int x = tid; x < NRELT * 64; x += 256)
        bws[x] = reinterpret_cast<const float4*>(g_bW)[x];
    __syncthreads();
    int idx = blockIdx.x * 256 + tid;       // NN*64 exactly
    int m = idx >> 6, q = idx & 63;
    unsigned mask = g_indmask[m];
    float invf = g_invfull[m];
    float4 s = make_float4(0.f, 0.f, 0.f, 0.f);
    #pragma unroll
    for (int i = 0; i < NRELT; i++) {
        if ((mask >> i) & 1u) {
            float4 b = bws[i * 64 + q];
            s.x += b.x; s.y += b.y; s.z += b.z; s.w += b.w;
        }
    }
    s.x *= invf; s.y *= invf; s.z *= invf; s.w *= invf;
    reinterpret_cast<float4*>(out)[idx] = s;
}

// ---------------- aggregation: one warp per CSR bin, X gathered from L2 -------
// Y[m][rel*256+k] = scale[rel][m] * sum_{edges} X[col][k], emitted as bf16 hi/lo.
__global__ void __launch_bounds__(256) k_agg(const float* __restrict__ feat) {
    unsigned gw = ((unsigned)blockIdx.x * blockDim.x + threadIdx.x) >> 5;  // bin
    int lane = threadIdx.x & 31;
    int rel = gw / NPAD;
    int m   = gw - rel * NPAD;
    int bin = (int)gw;

    float4 a0 = make_float4(0.f, 0.f, 0.f, 0.f);
    float4 a1 = make_float4(0.f, 0.f, 0.f, 0.f);
    int d = g_degi[bin];
    if (d > 0) {
        float s = g_scale[bin];
        int s0 = g_roff[bin];
        #pragma unroll 2
        for (int j = 0; j < d; j++) {
            int c = __ldg(&g_ecol[s0 + j]);
            const float4* xp = reinterpret_cast<const float4*>(feat + (size_t)c * DD);
            float4 v0 = __ldg(xp + 2 * lane);
            float4 v1 = __ldg(xp + 2 * lane + 1);
            a0.x += s * v0.x; a0.y += s * v0.y; a0.z += s * v0.z; a0.w += s * v0.w;
            a1.x += s * v1.x; a1.y += s * v1.y; a1.z += s * v1.z; a1.w += s * v1.w;
        }
    }
    // split 8 floats (cols 8*lane .. 8*lane+7) into bf16 hi/lo uint4s
    __nv_bfloat16 h0 = __float2bfloat16(a0.x), h1 = __float2bfloat16(a0.y);
    __nv_bfloat16 h2 = __float2bfloat16(a0.z), h3 = __float2bfloat16(a0.w);
    __nv_bfloat16 h4 = __float2bfloat16(a1.x), h5 = __float2bfloat16(a1.y);
    __nv_bfloat16 h6 = __float2bfloat16(a1.z), h7 = __float2bfloat16(a1.w);
    uint4 hiv, lov;
    hiv.x = pack_bf2(h0, h1); hiv.y = pack_bf2(h2, h3);
    hiv.z = pack_bf2(h4, h5); hiv.w = pack_bf2(h6, h7);
    lov.x = pack_bf2(__float2bfloat16(a0.x - __bfloat162float(h0)),
                     __float2bfloat16(a0.y - __bfloat162float(h1)));
    lov.y = pack_bf2(__float2bfloat16(a0.z - __bfloat162float(h2)),
                     __float2bfloat16(a0.w - __bfloat162float(h3)));
    lov.z = pack_bf2(__float2bfloat16(a1.x - __bfloat162float(h4)),
                     __float2bfloat16(a1.y - __bfloat162float(h5)));
    lov.w = pack_bf2(__float2bfloat16(a1.z - __bfloat162float(h6)),
                     __float2bfloat16(a1.w - __bfloat162float(h7)));
    size_t ob = (size_t)m * 512 + rel * 32 + lane;   // uint4 units (8 bf16 each)
    reinterpret_cast<uint4*>(g_Yhi)[ob] = hiv;
    reinterpret_cast<uint4*>(g_Ylo)[ob] = lov;
}

// ---------------- GEMM: out += Y[NPAD,4096] @ Wcat[4096,256] -------------------
__device__ __forceinline__ void load_stage(uint32_t sb, int tid, int rowBase, int kb) {
    #pragma unroll
    for (int p = 0; p < 4; p++) {
        int idx = tid + p * 256;          // 0..1023: A tile 128 rows x 64 k
        int row = idx >> 3, ch = idx & 7;
        uint32_t so = sw128(row * 128 + ch * 16);
        size_t ga = (size_t)(rowBase + row) * KTOT + kb + ch * 8;
        cp16(sb + A_HI + so, g_Yhi + ga);
        cp16(sb + A_LO + so, g_Ylo + ga);
    }
    #pragma unroll
    for (int p = 0; p < 8; p++) {
        int idx = tid + p * 256;          // 0..2047: B tile 256 rows x 64 k
        int row = idx >> 3, ch = idx & 7;
        uint32_t so = sw128(row * 128 + ch * 16);
        size_t gb = (size_t)row * KTOT + kb + ch * 8;
        cp16(sb + B_HI + so, g_Whi + gb);
        cp16(sb + B_LO + so, g_Wlo + gb);
    }
    asm volatile("cp.async.commit_group;" ::: "memory");
}

__global__ void __launch_bounds__(256, 1) k_gemm(float* __restrict__ out) {
    extern __shared__ char smraw[];
    uint32_t sraw = (uint32_t)__cvta_generic_to_shared(smraw);
    uint32_t sbase = (sraw + 1023) & ~1023u;

    const int tid = threadIdx.x;
    const int lane = tid & 31;
    const int wid = tid >> 5;
    const int wm = wid >> 1;          // 0..3 (32 rows each)
    const int wn = wid & 1;           // 0..1 (128 cols each)
    const int rowBase = blockIdx.x * 128;

    float acc[2][16][4] = {};

    uint32_t aoff[2], boff[8];
    #pragma unroll
    for (int mf = 0; mf < 2; mf++)
        aoff[mf] = sw128((wm * 32 + mf * 16 + (lane & 15)) * 128 + (lane >> 4) * 16);
    #pragma unroll
    for (int nf = 0; nf < 8; nf++)
        boff[nf] = sw128((wn * 128 + nf * 16 + (lane & 15)) * 128 + (lane >> 4) * 16);

    load_stage(sbase, tid, rowBase, 0);

    for (int t = 0; t < KTOT / 64; t++) {
        asm volatile("cp.async.wait_group 0;" ::: "memory");
        __syncthreads();
        if (t < KTOT / 64 - 1)
            load_stage(sbase + ((t + 1) & 1) * STAGE, tid, rowBase, (t + 1) * 64);
        uint32_t sb = sbase + (t & 1) * STAGE;

        #pragma unroll
        for (int ks = 0; ks < 4; ks++) {
            // ks*32 hits swizzle XOR-target bits [5:6] -> compose with XOR.
            uint32_t kx = ks * 32;
            uint32_t ah[2][4], al[2][4], bh[8][4], bl[8][4];
            #pragma unroll
            for (int mf = 0; mf < 2; mf++) {
                uint32_t o = aoff[mf] ^ kx;
                ldsm4(ah[mf], sb + A_HI + o);
                ldsm4(al[mf], sb + A_LO + o);
            }
            #pragma unroll
            for (int nf = 0; nf < 8; nf++) {
                uint32_t o = boff[nf] ^ kx;
                ldsm4(bh[nf], sb + B_HI + o);
                ldsm4(bl[nf], sb + B_LO + o);
            }
            #pragma unroll
            for (int mf = 0; mf < 2; mf++) {
                #pragma unroll
                for (int j = 0; j < 16; j++) {
                    uint32_t b0h = bh[j >> 1][j & 1], b1h = bh[j >> 1][(j & 1) + 2];
                    uint32_t b0l = bl[j >> 1][j & 1], b1l = bl[j >> 1][(j & 1) + 2];
                    mma_bf16(acc[mf][j], ah[mf], b0h, b1h);   // hi*hi
                    mma_bf16(acc[mf][j], al[mf], b0h, b1h);   // lo*hi
                    mma_bf16(acc[mf][j], ah[mf], b0l, b1l);   // hi*lo
                }
            }
        }
    }

    // Epilogue: out += acc (out pre-initialized with bias term by k_init)
    float* ob = out + (size_t)(rowBase + wm * 32) * DD + wn * 128;
    #pragma unroll
    for (int mf = 0; mf < 2; mf++) {
        #pragma unroll
        for (int j = 0; j < 16; j++) {
            int r0 = mf * 16 + (lane >> 2);
            int c  = j * 8 + (lane & 3) * 2;
            int gr = rowBase + wm * 32 + r0;
            if (gr < NN) {
                float2* p = reinterpret_cast<float2*>(ob + (size_t)r0 * DD + c);
                float2 v = *p;
                v.x += acc[mf][j][0]; v.y += acc[mf][j][1];
                *p = v;
            }
            if (gr + 8 < NN) {
                float2* p = reinterpret_cast<float2*>(ob + (size_t)(r0 + 8) * DD + c);
                float2 v = *p;
                v.x += acc[mf][j][2]; v.y += acc[mf][j][3];
                *p = v;
            }
        }
    }
}

// ---------------- launch ------------------------------------------------------
extern "C" void kernel_launch(void* const* d_in, const int* in_sizes, int n_in,
                              void* d_out, int out_size) {
    const float* features  = (const float*)d_in[0];
    const float* w         = (const float*)d_in[1];
    const float* bias      = (const float*)d_in[2];
    const float* w_t       = (const float*)d_in[3];
    const float* bias_t    = (const float*)d_in[4];
    const int*   adj_row   = (const int*)d_in[5];
    const int*   adj_col   = (const int*)d_in[6];
    const int*   adj_t_row = (const int*)d_in[7];
    const int*   adj_t_col = (const int*)d_in[8];
    float* out = (float*)d_out;

    cudaFuncSetAttribute(k_gemm, cudaFuncAttributeMaxDynamicSharedMemorySize, SMEM_GEMM);

    k_prepW<<<(DD * KTOT) / 256, 256>>>(w, w_t);
    k_bw<<<NRELT, 256>>>(bias, w, bias_t, w_t);
    k_zdeg<<<NB / 256, 256>>>();
    k_deg<<<(NRELT * EE) / 256, 256>>>(adj_row, adj_t_row);   // profiled slot
    k_scanA<<<NBLK, 256>>>();
    k_scanB<<<1, 256>>>();
    k_scanC<<<NBLK, 256>>>();
    k_ecol<<<(NRELT * EE) / 256, 256>>>(adj_row, adj_col, adj_t_row, adj_t_col);
    k_norm<<<(NPAD + 255) / 256, 256>>>();
    k_init<<<(NN * 64) / 256, 256>>>(out);
    k_agg<<<NB / 8, 256>>>(features);
    k_gemm<<<NPAD / 128, 256, SMEM_GEMM>>>(out);
}